// round 10
// baseline (speedup 1.0000x reference)
#include <cuda_runtime.h>
#include <cuda_fp16.h>
#include <stdint.h>

#define NHEADS 16
#define DMODEL 2048
#define DHEAD  128
#define ROTD   64
#define BATCHN 4
#define SEQL   2048
#define MTOT   (BATCHN*SEQL)     /* 8192 */
#define KTOT   DMODEL            /* 2048 */
#define NSEG   (NHEADS*DHEAD)    /* 2048 */
#define NTOT   (3*NSEG)          /* 6144 */

#define BM 128
#define BN 128
#define BK 64
#define STAGES 3
#define THREADS 128              /* 4 warps, 2x2 grid of 64x64 warp tiles */

#define RES_F4  ((MTOT*DMODEL)/4)            /* 4194304 float4 */
#define GRID_X  (NTOT/BN)                    /* 48 */
#define GRID_Y  (MTOT/BM)                    /* 64 */
#define RSTRIDE (GRID_X*GRID_Y*THREADS)      /* 393216 */

// ---- scratch (device globals: no allocation allowed) ----
__device__ __half g_Xh[(size_t)MTOT * KTOT];   // x in fp16, row-major [M][K]
__device__ __half g_Wh[(size_t)NTOT * KTOT];   // packed B^T in fp16, [N][K]
__device__ float2 g_rope[SEQL * (ROTD / 2)];   // (cos, sin) per (pos, pair)

// ------------------------------------------------------------------
// Prologue: fp32 x -> fp16
// ------------------------------------------------------------------
__global__ void convert_x_kernel(const float4* __restrict__ x, int n4) {
    int i = blockIdx.x * blockDim.x + threadIdx.x;
    if (i < n4) {
        float4 v = x[i];
        __half2 h0 = __floats2half2_rn(v.x, v.y);
        __half2 h1 = __floats2half2_rn(v.z, v.w);
        uint2 u;
        u.x = *reinterpret_cast<uint32_t*>(&h0);
        u.y = *reinterpret_cast<uint32_t*>(&h1);
        reinterpret_cast<uint2*>(g_Xh)[i] = u;
    }
}

// ------------------------------------------------------------------
// Prologue: pack W_{Q,K,V} [16,2048,128] -> g_Wh [6144][2048] fp16
// ------------------------------------------------------------------
__global__ void pack_w_kernel(const float* __restrict__ Wq,
                              const float* __restrict__ Wk,
                              const float* __restrict__ Wv) {
    __shared__ float t[32][33];
    int h   = blockIdx.z & 15;
    int seg = blockIdx.z >> 4;
    const float* W = (seg == 0) ? Wq : (seg == 1) ? Wk : Wv;
    const float* base = W + (size_t)h * DMODEL * DHEAD;
    int d0 = blockIdx.x * 32;
    int e0 = blockIdx.y * 32;
    int tx = threadIdx.x, ty = threadIdx.y;
#pragma unroll
    for (int i = 0; i < 4; i++) {
        int dl = ty + i * 8;
        t[dl][tx] = base[(size_t)(d0 + dl) * DHEAD + e0 + tx];
    }
    __syncthreads();
#pragma unroll
    for (int i = 0; i < 4; i++) {
        int el = ty + i * 8;
        int n  = seg * NSEG + h * DHEAD + e0 + el;
        g_Wh[(size_t)n * KTOT + d0 + tx] = __float2half_rn(t[tx][el]);
    }
}

// ------------------------------------------------------------------
// Prologue: rotary table (double precision trig)
// ------------------------------------------------------------------
__global__ void rope_table_kernel() {
    int i = blockIdx.x * blockDim.x + threadIdx.x;
    if (i < SEQL * (ROTD / 2)) {
        int pos = i >> 5;        // ROTD/2 == 32
        int j   = i & 31;
        double freq = exp(log(10000.0) * (double)j / 32.0);
        double a = (double)pos / freq;
        g_rope[i] = make_float2((float)cos(a), (float)sin(a));
    }
}

// ------------------------------------------------------------------
// Main fused GEMM + bias + rotary + residual copy
// ------------------------------------------------------------------
__device__ __forceinline__ uint32_t smem_u32(const void* p) {
    uint32_t a;
    asm("{.reg .u64 t; cvta.to.shared.u64 t, %1; cvt.u32.u64 %0, t;}"
        : "=r"(a) : "l"(p));
    return a;
}

#define LDMX4(addr, r0, r1, r2, r3) \
    asm volatile("ldmatrix.sync.aligned.m8n8.x4.shared.b16 {%0,%1,%2,%3}, [%4];" \
                 : "=r"(r0), "=r"(r1), "=r"(r2), "=r"(r3) : "r"(addr))

extern "C" __global__ void __launch_bounds__(THREADS, 2)
qkv_gemm_kernel(const float* __restrict__ residual,
                const float* __restrict__ bQ, const float* __restrict__ bK,
                const float* __restrict__ bV, float* __restrict__ out) {
    extern __shared__ __half smem[];
    const uint32_t As_u = smem_u32(smem);
    const uint32_t Bs_u = As_u + STAGES * (BM * BK * 2);

    const int tid  = threadIdx.x;
    const int lane = tid & 31;
    const int warp = tid >> 5;
    const int wm = warp >> 1;  // 0..1 -> m offset *64
    const int wn = warp & 1;   // 0..1 -> n offset *64

    const int m0 = blockIdx.y * BM;
    const int n0 = blockIdx.x * BN;
    const int seg = n0 / NSEG;          // 0=q 1=k 2=v (block uniform)
    const int w0  = n0 - seg * NSEG;    // column within segment (mult of 128)

    // ldmatrix base offsets (swizzle XOR: row%8 == lane%8 for all fragments)
    const int lx7 = (lane & 7) << 4;
    const int kx0 = (lane >> 4);
    uint32_t r128a[4], r128b[4];
#pragma unroll
    for (int mt = 0; mt < 4; mt++)
        r128a[mt] = (wm * 64 + mt * 16 + (lane & 15)) * 128;
#pragma unroll
    for (int bt = 0; bt < 4; bt++)
        r128b[bt] = (wn * 64 + bt * 16 + (lane & 15)) * 128;

    auto load_stage = [&](int stg, int k0) {
        uint32_t abase = As_u + stg * (BM * BK * 2);
        uint32_t bbase = Bs_u + stg * (BN * BK * 2);
#pragma unroll
        for (int i = 0; i < 8; i++) {
            int id  = tid + i * THREADS;   // 0..1023
            int row = id >> 3;
            int c   = id & 7;
            int ch  = c ^ (row & 7);       // SW128 swizzle
            const __half* srcA = &g_Xh[(size_t)(m0 + row) * KTOT + k0 + c * 8];
            asm volatile("cp.async.cg.shared.global [%0], [%1], 16;\n"
                         :: "r"(abase + row * 128 + (ch << 4)), "l"(srcA) : "memory");
            const __half* srcB = &g_Wh[(size_t)(n0 + row) * KTOT + k0 + c * 8];
            asm volatile("cp.async.cg.shared.global [%0], [%1], 16;\n"
                         :: "r"(bbase + row * 128 + (ch << 4)), "l"(srcB) : "memory");
        }
    };

    float acc[4][8][4];
#pragma unroll
    for (int i = 0; i < 4; i++)
#pragma unroll
        for (int j = 0; j < 8; j++)
#pragma unroll
            for (int k = 0; k < 4; k++) acc[i][j][k] = 0.f;

    load_stage(0, 0);
    asm volatile("cp.async.commit_group;\n" ::: "memory");
    load_stage(1, BK);
    asm volatile("cp.async.commit_group;\n" ::: "memory");

    // ---- residual passthrough, hidden in the GEMM's memory slack ----
    {
        const float4* rsrc = reinterpret_cast<const float4*>(residual);
        float4* rdst = reinterpret_cast<float4*>(out);
        int rid = (blockIdx.y * GRID_X + blockIdx.x) * THREADS + tid;
#pragma unroll
        for (int j = 0; j < 11; j++) {
            int idx = rid + j * RSTRIDE;
            if (idx < RES_F4) rdst[idx] = rsrc[idx];
        }
    }

    const int KITERS = KTOT / BK;  // 32
    for (int kt = 0; kt < KITERS; kt++) {
        asm volatile("cp.async.wait_group 1;\n" ::: "memory");
        __syncthreads();
        if (kt + 2 < KITERS) load_stage((kt + 2) % STAGES, (kt + 2) * BK);
        asm volatile("cp.async.commit_group;\n" ::: "memory");

        uint32_t a_st = As_u + (kt % STAGES) * (BM * BK * 2);
        uint32_t b_st = Bs_u + (kt % STAGES) * (BN * BK * 2);
#pragma unroll
        for (int ks = 0; ks < 4; ks++) {
            int chA = (ks * 2 + kx0) << 4;   // pre-XOR column offset
            uint32_t fa[4][4], fb[8][2];
#pragma unroll
            for (int mt = 0; mt < 4; mt++) {
                uint32_t addr = a_st + r128a[mt] + (chA ^ lx7);
                LDMX4(addr, fa[mt][0], fa[mt][1], fa[mt][2], fa[mt][3]);
            }
#pragma unroll
            for (int bt = 0; bt < 4; bt++) {
                uint32_t addr = b_st + r128b[bt] + (chA ^ lx7);
                uint32_t r0, r1, r2, r3;
                LDMX4(addr, r0, r1, r2, r3);
                fb[bt * 2][0] = r0;     fb[bt * 2][1] = r2;
                fb[bt * 2 + 1][0] = r1; fb[bt * 2 + 1][1] = r3;
            }
#pragma unroll
            for (int mt = 0; mt < 4; mt++)
#pragma unroll
                for (int nt = 0; nt < 8; nt++)
                    asm volatile(
                        "mma.sync.aligned.m16n8k16.row.col.f32.f16.f16.f32 "
                        "{%0,%1,%2,%3}, {%4,%5,%6,%7}, {%8,%9}, {%0,%1,%2,%3};"
                        : "+f"(acc[mt][nt][0]), "+f"(acc[mt][nt][1]),
                          "+f"(acc[mt][nt][2]), "+f"(acc[mt][nt][3])
                        : "r"(fa[mt][0]), "r"(fa[mt][1]), "r"(fa[mt][2]), "r"(fa[mt][3]),
                          "r"(fb[nt][0]), "r"(fb[nt][1]));
        }
    }

    // -------- epilogue: bias + rotary, direct float2 stores ----
    const float* bias = (seg == 0) ? bQ : (seg == 1) ? bK : bV;
    const int cp = (lane & 3) << 1;           // column pair offset in nt block
    const bool dorope = (seg < 2) && (wn == 0);  // warp-uniform: cols 0..63

    float2 bv[8];
#pragma unroll
    for (int nt = 0; nt < 8; nt++)
        bv[nt] = *reinterpret_cast<const float2*>(&bias[w0 + wn * 64 + nt * 8 + cp]);

    size_t obase = (size_t)(1 + seg) * ((size_t)MTOT * NSEG);
#pragma unroll
    for (int mt = 0; mt < 4; mt++) {
#pragma unroll
        for (int hh = 0; hh < 2; hh++) {
            int rl  = wm * 64 + mt * 16 + (lane >> 2) + hh * 8;
            int pos = (m0 + rl) & (SEQL - 1);
            float* orow = &out[obase + (size_t)(m0 + rl) * NSEG + w0 + wn * 64];
            const float2* rrow = &g_rope[pos * (ROTD / 2)];
#pragma unroll
            for (int nt = 0; nt < 8; nt++) {
                int c = nt * 8 + cp;          // 0..63 within warp column block
                float v0 = acc[mt][nt][hh * 2 + 0] + bv[nt].x;
                float v1 = acc[mt][nt][hh * 2 + 1] + bv[nt].y;
                if (dorope) {
                    float2 cs = rrow[c >> 1];
                    float t0 = v0 * cs.x - v1 * cs.y;
                    v1 = v1 * cs.x + v0 * cs.y;
                    v0 = t0;
                }
                *reinterpret_cast<float2*>(&orow[c]) = make_float2(v0, v1);
            }
        }
    }
}

// ------------------------------------------------------------------
// Launch
// ------------------------------------------------------------------
extern "C" void kernel_launch(void* const* d_in, const int* in_sizes, int n_in,
                              void* d_out, int out_size) {
    const float* residual = (const float*)d_in[0];
    const float* x  = (const float*)d_in[1];
    const float* Wq = (const float*)d_in[2];
    const float* Wk = (const float*)d_in[3];
    const float* Wv = (const float*)d_in[4];
    const float* bQ = (const float*)d_in[5];
    const float* bK = (const float*)d_in[6];
    const float* bV = (const float*)d_in[7];
    float* out = (float*)d_out;

    cudaFuncSetAttribute(qkv_gemm_kernel,
                         cudaFuncAttributeMaxDynamicSharedMemorySize,
                         STAGES * (BM + BN) * BK * (int)sizeof(__half));

    // prologues
    int n4 = (MTOT * KTOT) / 4;
    convert_x_kernel<<<(n4 + 255) / 256, 256>>>(
        reinterpret_cast<const float4*>(x), n4);
    dim3 pw_grid(DMODEL / 32, DHEAD / 32, 48);
    pack_w_kernel<<<pw_grid, dim3(32, 8)>>>(Wq, Wk, Wv);
    rope_table_kernel<<<(SEQL * (ROTD / 2) + 255) / 256, 256>>>();

    // fused GEMM + bias + rotary + residual copy
    dim3 grid(GRID_X, GRID_Y);
    qkv_gemm_kernel<<<grid, THREADS,
                      STAGES * (BM + BN) * BK * sizeof(__half)>>>(
        residual, bQ, bK, bV, out);
}